// round 16
// baseline (speedup 1.0000x reference)
#include <cuda_runtime.h>
#include <cuda_fp16.h>
#include <math.h>
#include <stdint.h>

#define Bb 16
#define Pp 1024
#define Ee 1024
#define Hh 16
#define Dh 64

// Device-global scratch (allocation-free per harness rules)
__device__ __half g_xh[(size_t)Bb * Pp * Ee];        // x as fp16
__device__ __half g_wvh[(size_t)Ee * Ee];            // wv_w as fp16
__device__ __half g_owh[(size_t)Ee * Ee];            // out_w as fp16
__device__ __half g_vxT[(size_t)Bb * Hh * Dh * Pp];  // vx fp16, per head: [b][h][d][p]
__device__ __half g_att[(size_t)Bb * Pp * Ee];       // attention out fp16

__device__ __forceinline__ uint32_t pk(float a, float b) {
    __half2 h = __floats2half2_rn(a, b);
    return *(uint32_t*)&h;
}
__device__ __forceinline__ uint32_t smem_u32(const void* p) {
    uint32_t a;
    asm("{ .reg .u64 t; cvta.to.shared.u64 t, %1; cvt.u32.u64 %0, t; }"
        : "=r"(a) : "l"(p));
    return a;
}
__device__ __forceinline__ void cpa16(uint32_t dst, const void* src) {
    asm volatile("cp.async.cg.shared.global [%0], [%1], 16;" :: "r"(dst), "l"(src));
}
#define CP_COMMIT() asm volatile("cp.async.commit_group;" ::: "memory")
#define CP_WAIT0() asm volatile("cp.async.wait_group 0;" ::: "memory")
#define CP_WAIT1() asm volatile("cp.async.wait_group 1;" ::: "memory")

#define MMA_F16(c, a, b)                                               \
    asm volatile(                                                      \
        "mma.sync.aligned.m16n8k16.row.col.f32.f16.f16.f32 "           \
        "{%0,%1,%2,%3}, {%4,%5,%6,%7}, {%8,%9}, {%0,%1,%2,%3};"        \
        : "+f"((c)[0]), "+f"((c)[1]), "+f"((c)[2]), "+f"((c)[3])       \
        : "r"((a)[0]), "r"((a)[1]), "r"((a)[2]), "r"((a)[3]),          \
          "r"((b)[0]), "r"((b)[1]))

// fp32 -> fp16 elementwise (8 per thread, grid-stride)
__global__ void cvt_fp16(const float* __restrict__ s, __half* __restrict__ d,
                         int n) {
    for (int i = (blockIdx.x * blockDim.x + threadIdx.x) * 8; i < n;
         i += gridDim.x * blockDim.x * 8) {
        float4 a = *(const float4*)(s + i);
        float4 b = *(const float4*)(s + i + 4);
        uint4 o;
        o.x = pk(a.x, a.y); o.y = pk(a.z, a.w);
        o.z = pk(b.x, b.y); o.w = pk(b.z, b.w);
        *(uint4*)(d + i) = o;
    }
}

// C[M,N] = A[M,K] @ B[N,K]^T + bias[N], fp16 inputs, fp32 accum.
// 128x128 block, 8 warps as 2x4, warp tile 64x32, K-tile 32,
// 3-stage cp.async pipeline (R13/R15-proven: ~121us). Row pitch 20 u32.
// TRANSV=true: C fp16 transposed per head [b][h][d][p]; else C fp32.
#define GST 20
#define G_STAGE (2 * 128 * GST)  // u32 per stage (A + B)
template <bool TRANSV>
__global__ void __launch_bounds__(256, 2) gemm_fp16(
    const __half* __restrict__ A, const __half* __restrict__ Bw,
    const float* __restrict__ bias, void* __restrict__ Cv,
    int M, int N, int K)
{
    extern __shared__ uint32_t gsm[];
    const uint32_t smb = smem_u32(gsm);

    const int tid  = threadIdx.x;
    const int lane = tid & 31;
    const int wid  = tid >> 5;
    const int wm   = wid >> 2;
    const int wn   = wid & 3;
    const int grp  = lane >> 2;
    const int thr  = lane & 3;

    const int rowA0 = blockIdx.y * 128;
    const int colB0 = blockIdx.x * 128;

    const int cr = tid >> 2;
    const int cc = tid & 3;
    const __half* Ap = A  + (size_t)(rowA0 + cr) * K + cc * 8;
    const __half* Bp = Bw + (size_t)(colB0 + cr) * K + cc * 8;

#define G_LOAD(kt, s)                                                        \
    do {                                                                     \
        uint32_t ab  = smb + (s) * (G_STAGE * 4);                            \
        uint32_t bb2 = ab + 128 * GST * 4;                                   \
        _Pragma("unroll")                                                    \
        for (int j = 0; j < 2; j++) {                                        \
            uint32_t off = (cr + j * 64) * (GST * 4) + cc * 16;              \
            cpa16(ab + off,  Ap + (kt) * 32 + (size_t)j * 64 * K);           \
            cpa16(bb2 + off, Bp + (kt) * 32 + (size_t)j * 64 * K);           \
        }                                                                    \
    } while (0)

#define G_COMPUTE(s)                                                         \
    do {                                                                     \
        const uint32_t* As = gsm + (s) * G_STAGE;                            \
        const uint32_t* Bs = As + 128 * GST;                                 \
        _Pragma("unroll")                                                    \
        for (int kk = 0; kk < 16; kk += 8) {                                 \
            uint32_t af[4][4];                                               \
            _Pragma("unroll")                                                \
            for (int mt = 0; mt < 4; mt++) {                                 \
                int base = (wm * 64 + mt * 16 + grp) * GST + kk + thr;       \
                af[mt][0] = As[base];                                        \
                af[mt][1] = As[base + 8 * GST];                              \
                af[mt][2] = As[base + 4];                                    \
                af[mt][3] = As[base + 8 * GST + 4];                          \
            }                                                                \
            _Pragma("unroll")                                                \
            for (int nt = 0; nt < 4; nt++) {                                 \
                uint32_t bf[2];                                              \
                int bbx = (wn * 32 + nt * 8 + grp) * GST + kk + thr;         \
                bf[0] = Bs[bbx];                                             \
                bf[1] = Bs[bbx + 4];                                         \
                _Pragma("unroll")                                            \
                for (int mt = 0; mt < 4; mt++)                               \
                    MMA_F16(acc[mt][nt], af[mt], bf);                        \
            }                                                                \
        }                                                                    \
    } while (0)

    float acc[4][4][4];
#pragma unroll
    for (int mt = 0; mt < 4; mt++)
#pragma unroll
        for (int nt = 0; nt < 4; nt++)
#pragma unroll
            for (int r = 0; r < 4; r++) acc[mt][nt][r] = 0.f;

    const int T = K / 32;  // 32
    G_LOAD(0, 0); CP_COMMIT();
    G_LOAD(1, 1); CP_COMMIT();

    for (int t = 0; t < T; t++) {
        CP_WAIT1();            // group for tile t complete
        __syncthreads();       // all warps past tile t-1 compute
        G_COMPUTE(t % 3);
        if (t + 2 < T) G_LOAD(t + 2, (t + 2) % 3);
        CP_COMMIT();           // exactly one commit per iter (may be empty)
    }

#pragma unroll
    for (int mt = 0; mt < 4; mt++) {
        const int row = rowA0 + wm * 64 + mt * 16 + grp;
#pragma unroll
        for (int nt = 0; nt < 4; nt++) {
            const int col = colB0 + wn * 32 + nt * 8 + thr * 2;
            float2 bz = *(const float2*)(bias + col);
            if (!TRANSV) {
                float* C = (float*)Cv;
                float2 v;
                v.x = acc[mt][nt][0] + bz.x;
                v.y = acc[mt][nt][1] + bz.y;
                *(float2*)(C + (size_t)row * N + col) = v;
                v.x = acc[mt][nt][2] + bz.x;
                v.y = acc[mt][nt][3] + bz.y;
                *(float2*)(C + (size_t)(row + 8) * N + col) = v;
            } else {
                __half* C = (__half*)Cv;
                const int bx = row >> 10;
                const int p  = row & 1023;
                const size_t d0 = ((size_t)(bx * Hh + (col >> 6)) * Dh + (col & 63)) * Pp;
                const size_t d1 = d0 + Pp;  // col+1 stays in head (col even)
                C[d0 + p]     = __float2half_rn(acc[mt][nt][0] + bz.x);
                C[d1 + p]     = __float2half_rn(acc[mt][nt][1] + bz.y);
                C[d0 + p + 8] = __float2half_rn(acc[mt][nt][2] + bz.x);
                C[d1 + p + 8] = __float2half_rn(acc[mt][nt][3] + bz.y);
            }
        }
    }
#undef G_LOAD
#undef G_COMPUTE
}

// Fused bilinear attention, fp16 mma (fp32 accum + fp32 softmax).
// One (b,h) x 128 queries per block, 4 warps (32q x 64k warp tile).
// K and V tiles double-buffered via cp.async, ONE group in flight
// (committed a full iteration ahead), ONE __syncthreads per iteration.
// Smem: XWs[128] Ps[128] Kb[2][64] Vb[2][64] rows of STP u32 = 73728 B.
#define STP 36
#define KB0 (256 * STP)
#define VB0 (384 * STP)
__global__ void __launch_bounds__(128, 2) attn_mma(
    const __half* __restrict__ xh, const float* __restrict__ watt,
    const float* __restrict__ bias, const __half* __restrict__ vxT,
    __half* __restrict__ outp)
{
    extern __shared__ uint32_t sm[];
    const uint32_t smb = smem_u32(sm);
    uint32_t* XWs = sm;                  // [128][STP] fp16 XW (scaled)
    uint32_t* Ps  = sm + 128 * STP;      // [128][STP] Xq then P tiles

    const int tid  = threadIdx.x;
    const int lane = tid & 31;
    const int wid  = tid >> 5;       // 0..3
    const int grp  = lane >> 2;
    const int thr  = lane & 3;
    const int m0   = wid * 32;

    const int q0 = blockIdx.x * 128;
    const int bh = blockIdx.y;
    const int b  = bh >> 4;
    const int h  = bh & 15;

    const __half* xb  = xh + (size_t)b * Pp * Ee + h * Dh;
    const __half* vtb = vxT + (size_t)bh * Dh * Pp;
    const float*  bb  = bias + (size_t)h * Pp * Pp;

    // row/chunk map for 64-row tiles: f = tid + r*128 -> row f>>3, chunk f&7
    // (64 rows x 8 chunks = 512 slots = 128 thr x 4)

    // Prologue A: issue K(0) -> Kb[0], V(0) -> Vb[0] (group 0)
#pragma unroll
    for (int r = 0; r < 4; r++) {
        int f = tid + r * 128;
        int row = f >> 3, c = f & 7;
        cpa16(smb + (KB0 + row * STP) * 4 + c * 16,
              xb + (size_t)row * Ee + c * 8);
        cpa16(smb + (VB0 + row * STP) * 4 + c * 16,
              vtb + (size_t)row * Pp + c * 8);
    }
    CP_COMMIT();

    // Prologue B: Xq -> Ps (plain), W^T -> Kb[1] region (plain scatter)
#pragma unroll
    for (int r = 0; r < 8; r++) {
        int f = tid + r * 128;
        int q = f >> 3, c = f & 7;
        *(uint4*)(&Ps[q * STP + c * 4]) =
            *(const uint4*)(xb + (size_t)(q0 + q) * Ee + c * 8);
    }
    {
        const float* Wp = watt + (size_t)h * Dh * Dh;
        __half* Wh = (__half*)(sm + KB0 + 64 * STP);  // Kb[1] region
#pragma unroll
        for (int r = 0; r < 8; r++) {
            int idx = tid + r * 128;
            int d = idx >> 4, e = (idx & 15) * 4;
            float4 v = *(const float4*)(Wp + d * Dh + e);
            Wh[(e + 0) * (2 * STP) + d] = __float2half_rn(v.x);
            Wh[(e + 1) * (2 * STP) + d] = __float2half_rn(v.y);
            Wh[(e + 2) * (2 * STP) + d] = __float2half_rn(v.z);
            Wh[(e + 3) * (2 * STP) + d] = __float2half_rn(v.w);
        }
    }
    __syncthreads();

    // Phase 1: XW = (Xq @ W) / 8 -> XWs (fp16). W^T lives in Kb[1].
    {
        const uint32_t* Ws = sm + KB0 + 64 * STP;
        float c2a[2][8][4];
#pragma unroll
        for (int mt = 0; mt < 2; mt++)
#pragma unroll
            for (int nt = 0; nt < 8; nt++)
#pragma unroll
                for (int r = 0; r < 4; r++) c2a[mt][nt][r] = 0.f;
#pragma unroll
        for (int kk = 0; kk < 32; kk += 8) {
            uint32_t af[2][4];
#pragma unroll
            for (int mt = 0; mt < 2; mt++) {
                int base = (m0 + mt * 16 + grp) * STP + kk + thr;
                af[mt][0] = Ps[base];
                af[mt][1] = Ps[base + 8 * STP];
                af[mt][2] = Ps[base + 4];
                af[mt][3] = Ps[base + 8 * STP + 4];
            }
#pragma unroll
            for (int nt = 0; nt < 8; nt++) {
                uint32_t bf[2];
                bf[0] = Ws[(nt * 8 + grp) * STP + kk + thr];
                bf[1] = Ws[(nt * 8 + grp) * STP + kk + 4 + thr];
#pragma unroll
                for (int mt = 0; mt < 2; mt++)
                    MMA_F16(c2a[mt][nt], af[mt], bf);
            }
        }
        __syncthreads();  // everyone done reading Ps (Xq) and Kb[1] (W^T)
#pragma unroll
        for (int mt = 0; mt < 2; mt++)
#pragma unroll
            for (int nt = 0; nt < 8; nt++) {
                int r0 = (m0 + mt * 16 + grp) * STP;
                int r1 = (m0 + mt * 16 + 8 + grp) * STP;
                XWs[r0 + nt * 4 + thr] = pk(c2a[mt][nt][0] * 0.125f,
                                            c2a[mt][nt][1] * 0.125f);
                XWs[r1 + nt * 4 + thr] = pk(c2a[mt][nt][2] * 0.125f,
                                            c2a[mt][nt][3] * 0.125f);
            }
    }
    // (XWs is warp-local rows for the S-mma reads; no barrier needed here —
    //  the top-of-loop barrier orders everything anyway.)

    float o[2][8][4];
#pragma unroll
    for (int mt = 0; mt < 2; mt++)
#pragma unroll
        for (int dt = 0; dt < 8; dt++)
#pragma unroll
            for (int r = 0; r < 4; r++) o[mt][dt][r] = 0.f;
    float mr[4], lr[4];
#pragma unroll
    for (int i = 0; i < 4; i++) { mr[i] = -INFINITY; lr[i] = 0.f; }

    for (int kb = 0; kb < 16; kb++) {
        const int k0 = kb * 64;
        const int cur = kb & 1;

        CP_WAIT0();        // K/V(kb) complete (sole outstanding group)
        __syncthreads();   // all warps past iter kb-1; buffers safe to reuse

        // Prefetch K(kb+1), V(kb+1) into the other buffer (group kb+1)
        if (kb < 15) {
            const int nb = cur ^ 1;
#pragma unroll
            for (int r = 0; r < 4; r++) {
                int f = tid + r * 128;
                int row = f >> 3, c = f & 7;
                cpa16(smb + (KB0 + (nb * 64 + row) * STP) * 4 + c * 16,
                      xb + (size_t)(k0 + 64 + row) * Ee + c * 8);
                cpa16(smb + (VB0 + (nb * 64 + row) * STP) * 4 + c * 16,
                      vtb + (size_t)row * Pp + k0 + 64 + c * 8);
            }
            CP_COMMIT();
        }

        const uint32_t* Ks = sm + KB0 + cur * 64 * STP;
        const uint32_t* Vs = sm + VB0 + cur * 64 * STP;

        // S = XW @ Xk^T
        float s[2][8][4];
#pragma unroll
        for (int mt = 0; mt < 2; mt++)
#pragma unroll
            for (int nt = 0; nt < 8; nt++)
#pragma unroll
                for (int r = 0; r < 4; r++) s[mt][nt][r] = 0.f;
#pragma unroll
        for (int kk = 0; kk < 32; kk += 8) {
            uint32_t af[2][4];
#pragma unroll
            for (int mt = 0; mt < 2; mt++) {
                int base = (m0 + mt * 16 + grp) * STP + kk + thr;
                af[mt][0] = XWs[base];
                af[mt][1] = XWs[base + 8 * STP];
                af[mt][2] = XWs[base + 4];
                af[mt][3] = XWs[base + 8 * STP + 4];
            }
#pragma unroll
            for (int nt = 0; nt < 8; nt++) {
                uint32_t bf[2];
                bf[0] = Ks[(nt * 8 + grp) * STP + kk + thr];
                bf[1] = Ks[(nt * 8 + grp) * STP + kk + 4 + thr];
#pragma unroll
                for (int mt = 0; mt < 2; mt++)
                    MMA_F16(s[mt][nt], af[mt], bf);
            }
        }

        // bias + online softmax (fp32, quad shfl)
#pragma unroll
        for (int mt = 0; mt < 2; mt++) {
            const float* bp0 = bb + (size_t)(q0 + m0 + mt * 16 + grp) * Pp + k0;
            const float* bp1 = bp0 + 8 * Pp;
            float mx0 = -INFINITY, mx1 = -INFINITY;
#pragma unroll
            for (int nt = 0; nt < 8; nt++) {
                float2 bz0 = *(const float2*)(bp0 + nt * 8 + 2 * thr);
                float2 bz1 = *(const float2*)(bp1 + nt * 8 + 2 * thr);
                s[mt][nt][0] += bz0.x; s[mt][nt][1] += bz0.y;
                s[mt][nt][2] += bz1.x; s[mt][nt][3] += bz1.y;
                mx0 = fmaxf(mx0, fmaxf(s[mt][nt][0], s[mt][nt][1]));
                mx1 = fmaxf(mx1, fmaxf(s[mt][nt][2], s[mt][nt][3]));
            }
            mx0 = fmaxf(mx0, __shfl_xor_sync(0xffffffffu, mx0, 1));
            mx0 = fmaxf(mx0, __shfl_xor_sync(0xffffffffu, mx0, 2));
            mx1 = fmaxf(mx1, __shfl_xor_sync(0xffffffffu, mx1, 1));
            mx1 = fmaxf(mx1, __shfl_xor_sync(0xffffffffu, mx1, 2));
            const int i0 = 2 * mt, i1 = 2 * mt + 1;
            float mn0 = fmaxf(mr[i0], mx0), mn1 = fmaxf(mr[i1], mx1);
            float al0 = __expf(mr[i0] - mn0), al1 = __expf(mr[i1] - mn1);
            mr[i0] = mn0; mr[i1] = mn1;
            float ps0 = 0.f, ps1 = 0.f;
#pragma unroll
            for (int nt = 0; nt < 8; nt++) {
                s[mt][nt][0] = __expf(s[mt][nt][0] - mn0);
                s[mt][nt][1] = __expf(s[mt][nt][1] - mn0);
                s[mt][nt][2] = __expf(s[mt][nt][2] - mn1);
                s[mt][nt][3] = __expf(s[mt][nt][3] - mn1);
                ps0 += s[mt][nt][0] + s[mt][nt][1];
                ps1 += s[mt][nt][2] + s[mt][nt][3];
            }
            ps0 += __shfl_xor_sync(0xffffffffu, ps0, 1);
            ps0 += __shfl_xor_sync(0xffffffffu, ps0, 2);
            ps1 += __shfl_xor_sync(0xffffffffu, ps1, 1);
            ps1 += __shfl_xor_sync(0xffffffffu, ps1, 2);
            lr[i0] = lr[i0] * al0 + ps0;
            lr[i1] = lr[i1] * al1 + ps1;
#pragma unroll
            for (int dt = 0; dt < 8; dt++) {
                o[mt][dt][0] *= al0; o[mt][dt][1] *= al0;
                o[mt][dt][2] *= al1; o[mt][dt][3] *= al1;
            }
        }

        // P -> Ps (rows [m0, m0+32) — own warp only; cross-lane within warp)
#pragma unroll
        for (int mt = 0; mt < 2; mt++)
#pragma unroll
            for (int nt = 0; nt < 8; nt++) {
                int r0 = (m0 + mt * 16 + grp) * STP;
                int r1 = (m0 + mt * 16 + 8 + grp) * STP;
                Ps[r0 + nt * 4 + thr] = pk(s[mt][nt][0], s[mt][nt][1]);
                Ps[r1 + nt * 4 + thr] = pk(s[mt][nt][2], s[mt][nt][3]);
            }
        __syncwarp();  // P visible across lanes of this warp

        // O += P @ V  (V already resident in Vb[cur])
#pragma unroll
        for (int kk = 0; kk < 32; kk += 8) {
            uint32_t af[2][4];
#pragma unroll
            for (int mt = 0; mt < 2; mt++) {
                int base = (m0 + mt * 16 + grp) * STP + kk + thr;
                af[mt][0] = Ps[base];
                af[mt][1] = Ps[base + 8 * STP];
                af[mt][2] = Ps[base + 4];
                af[mt][3] = Ps[base + 8 * STP + 4];
            }
#pragma unroll
            for (int dt = 0; dt < 8; dt++) {
                uint32_t bf[2];
                bf[0] = Vs[(dt * 8 + grp) * STP + kk + thr];
                bf[1] = Vs[(dt * 8 + grp) * STP + kk + 4 + thr];
#pragma unroll
                for (int mt = 0; mt < 2; mt++)
                    MMA_F16(o[mt][dt], af[mt], bf);
            }
        }
    }

    // Normalize and write out as fp16, natural [b][p][e] layout
    __half* ob = outp + (size_t)b * Pp * Ee + h * Dh;
#pragma unroll
    for (int mt = 0; mt < 2; mt++) {
        const float li0 = 1.f / lr[2 * mt];
        const float li1 = 1.f / lr[2 * mt + 1];
        const int r0 = q0 + m0 + mt * 16 + grp;
#pragma unroll
        for (int dt = 0; dt < 8; dt++) {
            *(uint32_t*)(ob + (size_t)r0 * Ee + dt * 8 + 2 * thr) =
                pk(o[mt][dt][0] * li0, o[mt][dt][1] * li0);
            *(uint32_t*)(ob + (size_t)(r0 + 8) * Ee + dt * 8 + 2 * thr) =
                pk(o[mt][dt][2] * li1, o[mt][dt][3] * li1);
        }
    }
}

extern "C" void kernel_launch(void* const* d_in, const int* in_sizes, int n_in,
                              void* d_out, int out_size) {
    const float* x     = (const float*)d_in[0];
    const float* watt  = (const float*)d_in[1];
    const float* abias = (const float*)d_in[2];
    const float* wv_w  = (const float*)d_in[3];
    const float* wv_b  = (const float*)d_in[4];
    const float* out_w = (const float*)d_in[5];
    const float* out_b = (const float*)d_in[6];
    float* outp = (float*)d_out;

    __half *xhp, *wvhp, *owhp, *vxTp, *attp;
    cudaGetSymbolAddress((void**)&xhp, g_xh);
    cudaGetSymbolAddress((void**)&wvhp, g_wvh);
    cudaGetSymbolAddress((void**)&owhp, g_owh);
    cudaGetSymbolAddress((void**)&vxTp, g_vxT);
    cudaGetSymbolAddress((void**)&attp, g_att);

    const int gemm_smem = 3 * G_STAGE * 4;   // 61440 B
    const int attn_smem = 512 * STP * 4;     // 73728 B
    cudaFuncSetAttribute(gemm_fp16<true>,
                         cudaFuncAttributeMaxDynamicSharedMemorySize, gemm_smem);
    cudaFuncSetAttribute(gemm_fp16<false>,
                         cudaFuncAttributeMaxDynamicSharedMemorySize, gemm_smem);
    cudaFuncSetAttribute(attn_mma,
                         cudaFuncAttributeMaxDynamicSharedMemorySize, attn_smem);

    // 0) one-time fp16 conversions
    cvt_fp16<<<2048, 256>>>(x, xhp, Bb * Pp * Ee);
    cvt_fp16<<<512, 256>>>(wv_w, wvhp, Ee * Ee);
    cvt_fp16<<<512, 256>>>(out_w, owhp, Ee * Ee);

    dim3 gg(Ee / 128, (Bb * Pp) / 128);  // (8, 128)

    // 1) vxT[b][h][d][p] (fp16) = (x @ wv_w^T + wv_b) transposed per head
    gemm_fp16<true><<<gg, 256, gemm_smem>>>(xhp, wvhp, wv_b, vxTp,
                                            Bb * Pp, Ee, Ee);
    // 2) fused bilinear attention (fp16 mma), output fp16
    attn_mma<<<dim3(Pp / 128, Bb * Hh), 128, attn_smem>>>(xhp, watt, abias,
                                                          vxTp, attp);
    // 3) out = att @ out_w^T + out_b (fp32 out)
    gemm_fp16<false><<<gg, 256, gemm_smem>>>(attp, owhp, out_b, outp,
                                             Bb * Pp, Ee, Ee);
}

// round 17
// speedup vs baseline: 1.4840x; 1.4840x over previous
#include <cuda_runtime.h>
#include <cuda_fp16.h>
#include <math.h>
#include <stdint.h>

#define Bb 16
#define Pp 1024
#define Ee 1024
#define Hh 16
#define Dh 64

// Device-global scratch (allocation-free per harness rules)
__device__ __half g_xh[(size_t)Bb * Pp * Ee];        // x as fp16
__device__ __half g_wvh[(size_t)Ee * Ee];            // wv_w as fp16
__device__ __half g_owh[(size_t)Ee * Ee];            // out_w as fp16
__device__ __half g_vxT[(size_t)Bb * Hh * Dh * Pp];  // vx fp16, per head: [b][h][d][p]
__device__ __half g_att[(size_t)Bb * Pp * Ee];       // attention out fp16

__device__ __forceinline__ uint32_t pk(float a, float b) {
    __half2 h = __floats2half2_rn(a, b);
    return *(uint32_t*)&h;
}
__device__ __forceinline__ uint32_t smem_u32(const void* p) {
    uint32_t a;
    asm("{ .reg .u64 t; cvta.to.shared.u64 t, %1; cvt.u32.u64 %0, t; }"
        : "=r"(a) : "l"(p));
    return a;
}
__device__ __forceinline__ void cpa16(uint32_t dst, const void* src) {
    asm volatile("cp.async.cg.shared.global [%0], [%1], 16;" :: "r"(dst), "l"(src));
}
#define CP_COMMIT() asm volatile("cp.async.commit_group;" ::: "memory")
#define CP_WAIT1() asm volatile("cp.async.wait_group 1;" ::: "memory")

#define MMA_F16(c, a, b)                                               \
    asm volatile(                                                      \
        "mma.sync.aligned.m16n8k16.row.col.f32.f16.f16.f32 "           \
        "{%0,%1,%2,%3}, {%4,%5,%6,%7}, {%8,%9}, {%0,%1,%2,%3};"        \
        : "+f"((c)[0]), "+f"((c)[1]), "+f"((c)[2]), "+f"((c)[3])       \
        : "r"((a)[0]), "r"((a)[1]), "r"((a)[2]), "r"((a)[3]),          \
          "r"((b)[0]), "r"((b)[1]))

// fp32 -> fp16 elementwise (8 per thread, grid-stride)
__global__ void cvt_fp16(const float* __restrict__ s, __half* __restrict__ d,
                         int n) {
    for (int i = (blockIdx.x * blockDim.x + threadIdx.x) * 8; i < n;
         i += gridDim.x * blockDim.x * 8) {
        float4 a = *(const float4*)(s + i);
        float4 b = *(const float4*)(s + i + 4);
        uint4 o;
        o.x = pk(a.x, a.y); o.y = pk(a.z, a.w);
        o.z = pk(b.x, b.y); o.w = pk(b.z, b.w);
        *(uint4*)(d + i) = o;
    }
}

// C[M,N] = A[M,K] @ B[N,K]^T + bias[N], fp16 inputs, fp32 accum.
// 128x128 block, 8 warps as 2x4, warp tile 64x32, K-tile 32,
// 3-stage cp.async pipeline (R13/R15-proven: ~121us). Row pitch 20 u32.
// TRANSV=true: C fp16 transposed per head [b][h][d][p]; else C fp32.
#define GST 20
#define G_STAGE (2 * 128 * GST)  // u32 per stage (A + B)
template <bool TRANSV>
__global__ void __launch_bounds__(256, 2) gemm_fp16(
    const __half* __restrict__ A, const __half* __restrict__ Bw,
    const float* __restrict__ bias, void* __restrict__ Cv,
    int M, int N, int K)
{
    extern __shared__ uint32_t gsm[];
    const uint32_t smb = smem_u32(gsm);

    const int tid  = threadIdx.x;
    const int lane = tid & 31;
    const int wid  = tid >> 5;
    const int wm   = wid >> 2;
    const int wn   = wid & 3;
    const int grp  = lane >> 2;
    const int thr  = lane & 3;

    const int rowA0 = blockIdx.y * 128;
    const int colB0 = blockIdx.x * 128;

    const int cr = tid >> 2;
    const int cc = tid & 3;
    const __half* Ap = A  + (size_t)(rowA0 + cr) * K + cc * 8;
    const __half* Bp = Bw + (size_t)(colB0 + cr) * K + cc * 8;

#define G_LOAD(kt, s)                                                        \
    do {                                                                     \
        uint32_t ab  = smb + (s) * (G_STAGE * 4);                            \
        uint32_t bb2 = ab + 128 * GST * 4;                                   \
        _Pragma("unroll")                                                    \
        for (int j = 0; j < 2; j++) {                                        \
            uint32_t off = (cr + j * 64) * (GST * 4) + cc * 16;              \
            cpa16(ab + off,  Ap + (kt) * 32 + (size_t)j * 64 * K);           \
            cpa16(bb2 + off, Bp + (kt) * 32 + (size_t)j * 64 * K);           \
        }                                                                    \
    } while (0)

#define G_COMPUTE(s)                                                         \
    do {                                                                     \
        const uint32_t* As = gsm + (s) * G_STAGE;                            \
        const uint32_t* Bs = As + 128 * GST;                                 \
        _Pragma("unroll")                                                    \
        for (int kk = 0; kk < 16; kk += 8) {                                 \
            uint32_t af[4][4];                                               \
            _Pragma("unroll")                                                \
            for (int mt = 0; mt < 4; mt++) {                                 \
                int base = (wm * 64 + mt * 16 + grp) * GST + kk + thr;       \
                af[mt][0] = As[base];                                        \
                af[mt][1] = As[base + 8 * GST];                              \
                af[mt][2] = As[base + 4];                                    \
                af[mt][3] = As[base + 8 * GST + 4];                          \
            }                                                                \
            _Pragma("unroll")                                                \
            for (int nt = 0; nt < 4; nt++) {                                 \
                uint32_t bf[2];                                              \
                int bbx = (wn * 32 + nt * 8 + grp) * GST + kk + thr;         \
                bf[0] = Bs[bbx];                                             \
                bf[1] = Bs[bbx + 4];                                         \
                _Pragma("unroll")                                            \
                for (int mt = 0; mt < 4; mt++)                               \
                    MMA_F16(acc[mt][nt], af[mt], bf);                        \
            }                                                                \
        }                                                                    \
    } while (0)

    float acc[4][4][4];
#pragma unroll
    for (int mt = 0; mt < 4; mt++)
#pragma unroll
        for (int nt = 0; nt < 4; nt++)
#pragma unroll
            for (int r = 0; r < 4; r++) acc[mt][nt][r] = 0.f;

    const int T = K / 32;  // 32
    G_LOAD(0, 0); CP_COMMIT();
    G_LOAD(1, 1); CP_COMMIT();

    for (int t = 0; t < T; t++) {
        CP_WAIT1();            // group for tile t complete
        __syncthreads();       // all warps past tile t-1 compute
        G_COMPUTE(t % 3);
        if (t + 2 < T) G_LOAD(t + 2, (t + 2) % 3);
        CP_COMMIT();           // exactly one commit per iter (may be empty)
    }

#pragma unroll
    for (int mt = 0; mt < 4; mt++) {
        const int row = rowA0 + wm * 64 + mt * 16 + grp;
#pragma unroll
        for (int nt = 0; nt < 4; nt++) {
            const int col = colB0 + wn * 32 + nt * 8 + thr * 2;
            float2 bz = *(const float2*)(bias + col);
            if (!TRANSV) {
                float* C = (float*)Cv;
                float2 v;
                v.x = acc[mt][nt][0] + bz.x;
                v.y = acc[mt][nt][1] + bz.y;
                *(float2*)(C + (size_t)row * N + col) = v;
                v.x = acc[mt][nt][2] + bz.x;
                v.y = acc[mt][nt][3] + bz.y;
                *(float2*)(C + (size_t)(row + 8) * N + col) = v;
            } else {
                __half* C = (__half*)Cv;
                const int bx = row >> 10;
                const int p  = row & 1023;
                const size_t d0 = ((size_t)(bx * Hh + (col >> 6)) * Dh + (col & 63)) * Pp;
                const size_t d1 = d0 + Pp;  // col+1 stays in head (col even)
                C[d0 + p]     = __float2half_rn(acc[mt][nt][0] + bz.x);
                C[d1 + p]     = __float2half_rn(acc[mt][nt][1] + bz.y);
                C[d0 + p + 8] = __float2half_rn(acc[mt][nt][2] + bz.x);
                C[d1 + p + 8] = __float2half_rn(acc[mt][nt][3] + bz.y);
            }
        }
    }
#undef G_LOAD
#undef G_COMPUTE
}

// Fused bilinear attention, fp16 mma (fp32 accum + fp32 softmax).
// One (b,h) x 128 queries per block, 4 warps (32q x 64k warp tile).
// R15-proven barrier structure (3 syncs/iter). K/V tile loads are
// REGISTER-STAGED: LDG issued early (overlapping mma/softmax), STS at the
// exact points R15 filled the tiles. No smem-lifetime or sync changes.
#define STP 36
__global__ void __launch_bounds__(128, 2) attn_mma(
    const __half* __restrict__ xh, const float* __restrict__ watt,
    const float* __restrict__ bias, const __half* __restrict__ vxT,
    __half* __restrict__ outp)
{
    extern __shared__ uint32_t sm[];
    uint32_t* XWs = sm;                  // [128][STP] fp16 XW (scaled)
    uint32_t* Ps  = sm + 128 * STP;      // [128][STP] Xq then P tiles
    uint32_t* KVs = sm + 2 * 128 * STP;  // [64][STP]  W^T / Xk / V^T tiles

    const int tid  = threadIdx.x;
    const int lane = tid & 31;
    const int wid  = tid >> 5;       // 0..3
    const int grp  = lane >> 2;
    const int thr  = lane & 3;
    const int m0   = wid * 32;

    const int q0 = blockIdx.x * 128;
    const int bh = blockIdx.y;
    const int b  = bh >> 4;
    const int h  = bh & 15;

    const __half* xb  = xh + (size_t)b * Pp * Ee + h * Dh;
    const __half* vtb = vxT + (size_t)bh * Dh * Pp;
    const float*  bb  = bias + (size_t)h * Pp * Pp;

    // tile slot map: f = tid + r*128 -> row f>>3 (0..63), chunk f&7
    int trow[4], tch[4];
#pragma unroll
    for (int r = 0; r < 4; r++) {
        int f = tid + r * 128;
        trow[r] = f >> 3;
        tch[r]  = f & 7;
    }

    // Phase 0: Xq -> Ps; W^T -> KVs (half scatter)
#pragma unroll
    for (int r = 0; r < 8; r++) {
        int f = tid + r * 128;
        int q = f >> 3, c = f & 7;
        *(uint4*)(&Ps[q * STP + c * 4]) =
            *(const uint4*)(xb + (size_t)(q0 + q) * Ee + c * 8);
    }
    {
        const float* Wp = watt + (size_t)h * Dh * Dh;
        __half* KVh = (__half*)KVs;
#pragma unroll
        for (int r = 0; r < 8; r++) {
            int idx = tid + r * 128;
            int d = idx >> 4, e = (idx & 15) * 4;
            float4 v = *(const float4*)(Wp + d * Dh + e);
            KVh[(e + 0) * (2 * STP) + d] = __float2half_rn(v.x);
            KVh[(e + 1) * (2 * STP) + d] = __float2half_rn(v.y);
            KVh[(e + 2) * (2 * STP) + d] = __float2half_rn(v.z);
            KVh[(e + 3) * (2 * STP) + d] = __float2half_rn(v.w);
        }
    }
    __syncthreads();

    // Phase 1: XW = (Xq @ W) / 8 -> XWs (fp16)
    {
        float c2a[2][8][4];
#pragma unroll
        for (int mt = 0; mt < 2; mt++)
#pragma unroll
            for (int nt = 0; nt < 8; nt++)
#pragma unroll
                for (int r = 0; r < 4; r++) c2a[mt][nt][r] = 0.f;
#pragma unroll
        for (int kk = 0; kk < 32; kk += 8) {
            uint32_t af[2][4];
#pragma unroll
            for (int mt = 0; mt < 2; mt++) {
                int base = (m0 + mt * 16 + grp) * STP + kk + thr;
                af[mt][0] = Ps[base];
                af[mt][1] = Ps[base + 8 * STP];
                af[mt][2] = Ps[base + 4];
                af[mt][3] = Ps[base + 8 * STP + 4];
            }
#pragma unroll
            for (int nt = 0; nt < 8; nt++) {
                uint32_t bf[2];
                bf[0] = KVs[(nt * 8 + grp) * STP + kk + thr];
                bf[1] = KVs[(nt * 8 + grp) * STP + kk + 4 + thr];
#pragma unroll
                for (int mt = 0; mt < 2; mt++)
                    MMA_F16(c2a[mt][nt], af[mt], bf);
            }
        }
        __syncthreads();  // everyone done reading Ps (Xq) and KVs (W^T)
#pragma unroll
        for (int mt = 0; mt < 2; mt++)
#pragma unroll
            for (int nt = 0; nt < 8; nt++) {
                int r0 = (m0 + mt * 16 + grp) * STP;
                int r1 = (m0 + mt * 16 + 8 + grp) * STP;
                XWs[r0 + nt * 4 + thr] = pk(c2a[mt][nt][0] * 0.125f,
                                            c2a[mt][nt][1] * 0.125f);
                XWs[r1 + nt * 4 + thr] = pk(c2a[mt][nt][2] * 0.125f,
                                            c2a[mt][nt][3] * 0.125f);
            }
    }
    __syncthreads();

    float o[2][8][4];
#pragma unroll
    for (int mt = 0; mt < 2; mt++)
#pragma unroll
        for (int dt = 0; dt < 8; dt++)
#pragma unroll
            for (int r = 0; r < 4; r++) o[mt][dt][r] = 0.f;
    float mr[4], lr[4];
#pragma unroll
    for (int i = 0; i < 4; i++) { mr[i] = -INFINITY; lr[i] = 0.f; }

    // Register-stage Xk(0)
    uint4 kreg[4];
#pragma unroll
    for (int r = 0; r < 4; r++)
        kreg[r] = *(const uint4*)(xb + (size_t)trow[r] * Ee + tch[r] * 8);

    for (int kb = 0; kb < 16; kb++) {
        const int k0 = kb * 64;

        // Xk tile: STS from registers (same point R15 did its fill)
#pragma unroll
        for (int r = 0; r < 4; r++)
            *(uint4*)(&KVs[trow[r] * STP + tch[r] * 4]) = kreg[r];
        __syncthreads();

        // Register-stage V(kb): LDG overlaps S-mma + softmax
        uint4 vreg[4];
#pragma unroll
        for (int r = 0; r < 4; r++)
            vreg[r] = *(const uint4*)(vtb + (size_t)trow[r] * Pp + k0 + tch[r] * 8);

        // S = XW @ Xk^T
        float s[2][8][4];
#pragma unroll
        for (int mt = 0; mt < 2; mt++)
#pragma unroll
            for (int nt = 0; nt < 8; nt++)
#pragma unroll
                for (int r = 0; r < 4; r++) s[mt][nt][r] = 0.f;
#pragma unroll
        for (int kk = 0; kk < 32; kk += 8) {
            uint32_t af[2][4];
#pragma unroll
            for (int mt = 0; mt < 2; mt++) {
                int base = (m0 + mt * 16 + grp) * STP + kk + thr;
                af[mt][0] = XWs[base];
                af[mt][1] = XWs[base + 8 * STP];
                af[mt][2] = XWs[base + 4];
                af[mt][3] = XWs[base + 8 * STP + 4];
            }
#pragma unroll
            for (int nt = 0; nt < 8; nt++) {
                uint32_t bf[2];
                bf[0] = KVs[(nt * 8 + grp) * STP + kk + thr];
                bf[1] = KVs[(nt * 8 + grp) * STP + kk + 4 + thr];
#pragma unroll
                for (int mt = 0; mt < 2; mt++)
                    MMA_F16(s[mt][nt], af[mt], bf);
            }
        }

        // Register-stage Xk(kb+1): LDG overlaps softmax + PV
        if (kb < 15) {
#pragma unroll
            for (int r = 0; r < 4; r++)
                kreg[r] = *(const uint4*)(xb + (size_t)(k0 + 64 + trow[r]) * Ee +
                                          tch[r] * 8);
        }

        // bias + online softmax (fp32, quad shfl)
#pragma unroll
        for (int mt = 0; mt < 2; mt++) {
            const float* bp0 = bb + (size_t)(q0 + m0 + mt * 16 + grp) * Pp + k0;
            const float* bp1 = bp0 + 8 * Pp;
            float mx0 = -INFINITY, mx1 = -INFINITY;
#pragma unroll
            for (int nt = 0; nt < 8; nt++) {
                float2 bz0 = *(const float2*)(bp0 + nt * 8 + 2 * thr);
                float2 bz1 = *(const float2*)(bp1 + nt * 8 + 2 * thr);
                s[mt][nt][0] += bz0.x; s[mt][nt][1] += bz0.y;
                s[mt][nt][2] += bz1.x; s[mt][nt][3] += bz1.y;
                mx0 = fmaxf(mx0, fmaxf(s[mt][nt][0], s[mt][nt][1]));
                mx1 = fmaxf(mx1, fmaxf(s[mt][nt][2], s[mt][nt][3]));
            }
            mx0 = fmaxf(mx0, __shfl_xor_sync(0xffffffffu, mx0, 1));
            mx0 = fmaxf(mx0, __shfl_xor_sync(0xffffffffu, mx0, 2));
            mx1 = fmaxf(mx1, __shfl_xor_sync(0xffffffffu, mx1, 1));
            mx1 = fmaxf(mx1, __shfl_xor_sync(0xffffffffu, mx1, 2));
            const int i0 = 2 * mt, i1 = 2 * mt + 1;
            float mn0 = fmaxf(mr[i0], mx0), mn1 = fmaxf(mr[i1], mx1);
            float al0 = __expf(mr[i0] - mn0), al1 = __expf(mr[i1] - mn1);
            mr[i0] = mn0; mr[i1] = mn1;
            float ps0 = 0.f, ps1 = 0.f;
#pragma unroll
            for (int nt = 0; nt < 8; nt++) {
                s[mt][nt][0] = __expf(s[mt][nt][0] - mn0);
                s[mt][nt][1] = __expf(s[mt][nt][1] - mn0);
                s[mt][nt][2] = __expf(s[mt][nt][2] - mn1);
                s[mt][nt][3] = __expf(s[mt][nt][3] - mn1);
                ps0 += s[mt][nt][0] + s[mt][nt][1];
                ps1 += s[mt][nt][2] + s[mt][nt][3];
            }
            ps0 += __shfl_xor_sync(0xffffffffu, ps0, 1);
            ps0 += __shfl_xor_sync(0xffffffffu, ps0, 2);
            ps1 += __shfl_xor_sync(0xffffffffu, ps1, 1);
            ps1 += __shfl_xor_sync(0xffffffffu, ps1, 2);
            lr[i0] = lr[i0] * al0 + ps0;
            lr[i1] = lr[i1] * al1 + ps1;
#pragma unroll
            for (int dt = 0; dt < 8; dt++) {
                o[mt][dt][0] *= al0; o[mt][dt][1] *= al0;
                o[mt][dt][2] *= al1; o[mt][dt][3] *= al1;
            }
        }

        // P -> Ps (fp16 pairs)
#pragma unroll
        for (int mt = 0; mt < 2; mt++)
#pragma unroll
            for (int nt = 0; nt < 8; nt++) {
                int r0 = (m0 + mt * 16 + grp) * STP;
                int r1 = (m0 + mt * 16 + 8 + grp) * STP;
                Ps[r0 + nt * 4 + thr] = pk(s[mt][nt][0], s[mt][nt][1]);
                Ps[r1 + nt * 4 + thr] = pk(s[mt][nt][2], s[mt][nt][3]);
            }
        __syncthreads();  // all warps done reading Xk; P visible

        // V^T tile: STS from registers (same point R15 did its fill)
#pragma unroll
        for (int r = 0; r < 4; r++)
            *(uint4*)(&KVs[trow[r] * STP + tch[r] * 4]) = vreg[r];
        __syncthreads();

        // O += P @ V
#pragma unroll
        for (int kk = 0; kk < 32; kk += 8) {
            uint32_t af[2][4];
#pragma unroll
            for (int mt = 0; mt < 2; mt++) {
                int base = (m0 + mt * 16 + grp) * STP + kk + thr;
                af[mt][0] = Ps[base];
                af[mt][1] = Ps[base + 8 * STP];
                af[mt][2] = Ps[base + 4];
                af[mt][3] = Ps[base + 8 * STP + 4];
            }
#pragma unroll
            for (int dt = 0; dt < 8; dt++) {
                uint32_t bf[2];
                bf[0] = KVs[(dt * 8 + grp) * STP + kk + thr];
                bf[1] = KVs[(dt * 8 + grp) * STP + kk + 4 + thr];
#pragma unroll
                for (int mt = 0; mt < 2; mt++)
                    MMA_F16(o[mt][dt], af[mt], bf);
            }
        }
        __syncthreads();  // all warps done reading V before next Xk STS
    }

    // Normalize and write out as fp16, natural [b][p][e] layout
    __half* ob = outp + (size_t)b * Pp * Ee + h * Dh;
#pragma unroll
    for (int mt = 0; mt < 2; mt++) {
        const float li0 = 1.f / lr[2 * mt];
        const float li1 = 1.f / lr[2 * mt + 1];
        const int r0 = q0 + m0 + mt * 16 + grp;
#pragma unroll
        for (int dt = 0; dt < 8; dt++) {
            *(uint32_t*)(ob + (size_t)r0 * Ee + dt * 8 + 2 * thr) =
                pk(o[mt][dt][0] * li0, o[mt][dt][1] * li0);
            *(uint32_t*)(ob + (size_t)(r0 + 8) * Ee + dt * 8 + 2 * thr) =
                pk(o[mt][dt][2] * li1, o[mt][dt][3] * li1);
        }
    }
}

extern "C" void kernel_launch(void* const* d_in, const int* in_sizes, int n_in,
                              void* d_out, int out_size) {
    const float* x     = (const float*)d_in[0];
    const float* watt  = (const float*)d_in[1];
    const float* abias = (const float*)d_in[2];
    const float* wv_w  = (const float*)d_in[3];
    const float* wv_b  = (const float*)d_in[4];
    const float* out_w = (const float*)d_in[5];
    const float* out_b = (const float*)d_in[6];
    float* outp = (float*)d_out;

    __half *xhp, *wvhp, *owhp, *vxTp, *attp;
    cudaGetSymbolAddress((void**)&xhp, g_xh);
    cudaGetSymbolAddress((void**)&wvhp, g_wvh);
    cudaGetSymbolAddress((void**)&owhp, g_owh);
    cudaGetSymbolAddress((void**)&vxTp, g_vxT);
    cudaGetSymbolAddress((void**)&attp, g_att);

    const int gemm_smem = 3 * G_STAGE * 4;           // 61440 B
    const int attn_smem = (2 * 128 + 64) * STP * 4;  // 46080 B
    cudaFuncSetAttribute(gemm_fp16<true>,
                         cudaFuncAttributeMaxDynamicSharedMemorySize, gemm_smem);
    cudaFuncSetAttribute(gemm_fp16<false>,
                         cudaFuncAttributeMaxDynamicSharedMemorySize, gemm_smem);
    cudaFuncSetAttribute(attn_mma,
                         cudaFuncAttributeMaxDynamicSharedMemorySize, attn_smem);

    // 0) one-time fp16 conversions
    cvt_fp16<<<2048, 256>>>(x, xhp, Bb * Pp * Ee);
    cvt_fp16<<<512, 256>>>(wv_w, wvhp, Ee * Ee);
    cvt_fp16<<<512, 256>>>(out_w, owhp, Ee * Ee);

    dim3 gg(Ee / 128, (Bb * Pp) / 128);  // (8, 128)

    // 1) vxT[b][h][d][p] (fp16) = (x @ wv_w^T + wv_b) transposed per head
    gemm_fp16<true><<<gg, 256, gemm_smem>>>(xhp, wvhp, wv_b, vxTp,
                                            Bb * Pp, Ee, Ee);
    // 2) fused bilinear attention (fp16 mma), output fp16
    attn_mma<<<dim3(Pp / 128, Bb * Hh), 128, attn_smem>>>(xhp, watt, abias,
                                                          vxTp, attp);
    // 3) out = att @ out_w^T + out_b (fp32 out)
    gemm_fp16<false><<<gg, 256, gemm_smem>>>(attp, owhp, out_b, outp,
                                             Bb * Pp, Ee, Ee);
}